// round 2
// baseline (speedup 1.0000x reference)
#include <cuda_runtime.h>
#include <cuda_bf16.h>
#include <cstdint>

// Problem shape (fixed by reference)
constexpr int Bc = 2, Hc = 8, Sc = 2048, Dc = 64;
constexpr int QT = 16;   // query rows per CTA
constexpr int KT = 64;   // K/V rows per stage tile
constexpr int NTHREADS = 256;
constexpr int STG_LD = 68;  // padded leading dim for stage buffer

// smem: scores[QT][Sc] + q[QT][Dc] + stage[64][STG_LD]
constexpr int SM_SC  = QT * Sc;            // 32768 floats
constexpr int SM_Q   = QT * Dc;            // 1024 floats
constexpr int SM_STG = 64 * STG_LD;        // 4352 floats
constexpr size_t SMEM_BYTES = (size_t)(SM_SC + SM_Q + SM_STG) * sizeof(float); // 152576

__global__ void __launch_bounds__(NTHREADS, 1)
attn_kernel(const float* __restrict__ Q, const float* __restrict__ K,
            const float* __restrict__ V, const int* __restrict__ mask,
            const float* __restrict__ decay, float* __restrict__ out_o,
            float* __restrict__ out_p)
{
    extern __shared__ float sm[];
    float* sc  = sm;                 // [QT][Sc]
    float* qs  = sm + SM_SC;         // [QT][Dc]
    float* stg = qs + SM_Q;          // [64][STG_LD]

    const int t   = threadIdx.x;
    const int bid = blockIdx.x;
    const int qtiles = Sc / QT;              // 128
    const int bh = bid / qtiles;
    const int qt = bid % qtiles;
    const int b  = bh / Hc;
    const int q0 = qt * QT;

    const float* Qp = Q + ((size_t)bh * Sc + q0) * Dc;
    const float* Kp = K + (size_t)bh * Sc * Dc;
    const float* Vp = V + (size_t)bh * Sc * Dc;

    // ---- load Q tile, pre-scaled by 1/sqrt(D) ----
    {
        float4 v = ((const float4*)Qp)[t];   // 256 threads x float4 = 1024 floats
        v.x *= 0.125f; v.y *= 0.125f; v.z *= 0.125f; v.w *= 0.125f;
        ((float4*)qs)[t] = v;
    }
    __syncthreads();

    const int qi = t >> 4;          // 0..15
    const int kg = (t & 15) * 4;    // 0..60 (column group of 4)

    // ================= QK^T =================
    for (int k0 = 0; k0 < Sc; k0 += KT) {
        // stage K tile transposed: stg[d][k]
        const float4* src = (const float4*)(Kp + (size_t)k0 * Dc);
        #pragma unroll
        for (int r = 0; r < 4; ++r) {
            int idx = t + r * 256;          // float4 index within 64x64 tile
            float4 v = src[idx];
            int kk = idx >> 4;              // k row (16 float4 per row)
            int dd = (idx & 15) * 4;        // d offset
            stg[(dd + 0) * STG_LD + kk] = v.x;
            stg[(dd + 1) * STG_LD + kk] = v.y;
            stg[(dd + 2) * STG_LD + kk] = v.z;
            stg[(dd + 3) * STG_LD + kk] = v.w;
        }
        __syncthreads();

        float a0 = 0.f, a1 = 0.f, a2 = 0.f, a3 = 0.f;
        const float* qrow = &qs[qi * Dc];
        #pragma unroll 8
        for (int d = 0; d < Dc; ++d) {
            float qv = qrow[d];
            float4 kv = *(const float4*)&stg[d * STG_LD + kg];
            a0 = fmaf(qv, kv.x, a0);
            a1 = fmaf(qv, kv.y, a1);
            a2 = fmaf(qv, kv.z, a2);
            a3 = fmaf(qv, kv.w, a3);
        }
        float* srow = &sc[qi * Sc + k0 + kg];
        srow[0] = a0; srow[1] = a1; srow[2] = a2; srow[3] = a3;
        __syncthreads();
    }

    // ================= clip / mask / decay =================
    {
        const int*   mrow = mask  + ((size_t)b  * Sc + q0) * Sc;   // int32 mask
        const float* drow = decay + ((size_t)bh * Sc + q0) * Sc;
        #pragma unroll 4
        for (int i = t; i < QT * Sc; i += NTHREADS) {
            // i = qi2*Sc + k ; mrow/drow indexed by the same flat offset
            float s = sc[i];
            s = fminf(fmaxf(s, 1e-9f), 1e9f);
            s = mrow[i] ? s : -1e9f;
            s *= drow[i];
            sc[i] = s;
        }
    }
    __syncthreads();

    // ================= softmax per row + write p_attn =================
    {
        const int wid  = t >> 5;
        const int lane = t & 31;
        for (int r = wid; r < QT; r += 8) {
            float* row = &sc[r * Sc];
            float mx = -3.4e38f;
            #pragma unroll 4
            for (int k = lane; k < Sc; k += 32) mx = fmaxf(mx, row[k]);
            #pragma unroll
            for (int o = 16; o; o >>= 1) mx = fmaxf(mx, __shfl_xor_sync(0xffffffffu, mx, o));

            float sum = 0.f;
            #pragma unroll 4
            for (int k = lane; k < Sc; k += 32) {
                float e = __expf(row[k] - mx);
                row[k] = e;
                sum += e;
            }
            #pragma unroll
            for (int o = 16; o; o >>= 1) sum += __shfl_xor_sync(0xffffffffu, sum, o);
            float inv = 1.f / sum;

            float* gp = out_p + ((size_t)bh * Sc + q0 + r) * Sc;
            #pragma unroll 4
            for (int k = lane * 4; k < Sc; k += 128) {
                float4 e = *(float4*)&row[k];
                e.x *= inv; e.y *= inv; e.z *= inv; e.w *= inv;
                *(float4*)&row[k] = e;
                *(float4*)&gp[k]  = e;
            }
        }
    }
    __syncthreads();

    // ================= P @ V =================
    {
        float o0 = 0.f, o1 = 0.f, o2 = 0.f, o3 = 0.f;
        for (int k0 = 0; k0 < Sc; k0 += KT) {
            // stage V tile row-major: stg[k][d]
            const float4* src = (const float4*)(Vp + (size_t)k0 * Dc);
            #pragma unroll
            for (int r = 0; r < 4; ++r) {
                int idx = t + r * 256;
                int kk = idx >> 4;
                int dd = (idx & 15) * 4;
                *(float4*)&stg[kk * STG_LD + dd] = src[idx];
            }
            __syncthreads();

            const float* prow = &sc[qi * Sc + k0];
            #pragma unroll 8
            for (int kk = 0; kk < KT; ++kk) {
                float p = prow[kk];
                float4 vv = *(const float4*)&stg[kk * STG_LD + kg];
                o0 = fmaf(p, vv.x, o0);
                o1 = fmaf(p, vv.y, o1);
                o2 = fmaf(p, vv.z, o2);
                o3 = fmaf(p, vv.w, o3);
            }
            __syncthreads();
        }
        float4 ov = make_float4(o0, o1, o2, o3);
        *(float4*)(out_o + ((size_t)bh * Sc + q0 + qi) * Dc + kg) = ov;
    }
}

extern "C" void kernel_launch(void* const* d_in, const int* in_sizes, int n_in,
                              void* d_out, int out_size)
{
    const float* Q     = (const float*)d_in[0];
    const float* K     = (const float*)d_in[1];
    const float* V     = (const float*)d_in[2];
    const int*   mask  = (const int*)d_in[3];
    const float* decay = (const float*)d_in[4];

    float* out_o = (float*)d_out;                                   // [B,H,S,D]
    float* out_p = (float*)d_out + (size_t)Bc * Hc * Sc * Dc;       // [B,H,S,S]

    cudaFuncSetAttribute(attn_kernel, cudaFuncAttributeMaxDynamicSharedMemorySize,
                         (int)SMEM_BYTES);

    int blocks = Bc * Hc * (Sc / QT);   // 2048
    attn_kernel<<<blocks, NTHREADS, SMEM_BYTES>>>(Q, K, V, mask, decay, out_o, out_p);
}

// round 3
// speedup vs baseline: 2.3107x; 2.3107x over previous
#include <cuda_runtime.h>
#include <cstdint>

constexpr int Bc = 2, Hc = 8, Sc = 2048, Dc = 64;
constexpr int QT = 16;     // q rows per CTA
constexpr int KT = 256;    // k rows per stage tile
constexpr int NT = 256;    // threads

constexpr int SM_SC = QT * Sc;     // 32768 floats: scores [16][2048]
constexpr int SM_KT = Dc * KT;     // 16384 floats: K^T swizzled [64][256] / V [256][64]
constexpr int SM_QS = Dc * QT;     // 1024 floats: Q^T [64][16] / later O buf [16][64]
constexpr size_t SMEM_BYTES = (size_t)(SM_SC + SM_KT + SM_QS) * 4;  // 200704 B

__global__ void __launch_bounds__(NT, 1)
attn_kernel(const float* __restrict__ Q, const float* __restrict__ K,
            const float* __restrict__ V, const int* __restrict__ mask,
            const float* __restrict__ decay, float* __restrict__ out_o,
            float* __restrict__ out_p)
{
    extern __shared__ float sm[];
    float* sc = sm;                    // [16][2048]
    float* kt = sm + SM_SC;            // staging tile
    float* qs = sm + SM_SC + SM_KT;    // q^T, later O reduce buffer

    const int t   = threadIdx.x;
    const int bid = blockIdx.x;
    const int bh  = bid >> 7;              // 128 q-tiles per (b,h)
    const int q0  = (bid & 127) * QT;
    const int b   = bh >> 3;

    const float* Qp = Q + ((size_t)bh * Sc + q0) * Dc;
    const float* Kp = K + (size_t)bh * Sc * Dc;
    const float* Vp = V + (size_t)bh * Sc * Dc;

    // ---- Q^T into qs[d][16], pre-scaled by 1/sqrt(64) ----
    {
        int qr = t >> 4, dd = (t & 15) * 4;
        float4 v = ((const float4*)Qp)[t];
        qs[(dd + 0) * QT + qr] = v.x * 0.125f;
        qs[(dd + 1) * QT + qr] = v.y * 0.125f;
        qs[(dd + 2) * QT + qr] = v.z * 0.125f;
        qs[(dd + 3) * QT + qr] = v.w * 0.125f;
    }
    __syncthreads();

    // ================= QK^T (+ fused clip/mask/decay) =================
    // thread tile: 4 q-rows x 4 k-cols. qg in 0..3 (q rows qg*4..+3),
    // kg in 0..63 (k cols kg*4..+3).
    const int qg = t >> 6;
    const int kg = t & 63;

    for (int tile = 0; tile < Sc / KT; ++tile) {
        // stage K^T: row d holds 64 float4s; float4 (logical col f=k>>2) stored
        // at phys index f ^ ((d>>2)&7). Scalar within float4 = k&3.
        const float4* src = (const float4*)(Kp + (size_t)tile * KT * Dc);
        #pragma unroll
        for (int r = 0; r < 16; ++r) {
            int idx = t + r * NT;            // 4096 float4 in tile
            int kk  = idx >> 4;              // k row in tile (16 float4 per row)
            int dd  = (idx & 15) * 4;        // d offset (components along d)
            float4 v = src[idx];
            int x    = (dd >> 2) & 7;        // same for dd..dd+3
            int fph  = (((kk >> 2) ^ x) << 2) + (kk & 3);
            kt[(dd + 0) * KT + fph] = v.x;
            kt[(dd + 1) * KT + fph] = v.y;
            kt[(dd + 2) * KT + fph] = v.z;
            kt[(dd + 3) * KT + fph] = v.w;
        }

        // prefetch mask/decay for this thread's 4x4 output block (latency
        // hidden behind the d-loop)
        const int col0 = tile * KT + kg * 4;
        float4 dec[4];
        int4   msk[4];
        #pragma unroll
        for (int i = 0; i < 4; ++i) {
            int qr = qg * 4 + i;
            dec[i] = *(const float4*)&decay[((size_t)bh * Sc + q0 + qr) * Sc + col0];
            msk[i] = *(const int4*)  &mask [((size_t)b  * Sc + q0 + qr) * Sc + col0];
        }
        __syncthreads();   // staging visible

        float4 acc0 = {0,0,0,0}, acc1 = {0,0,0,0}, acc2 = {0,0,0,0}, acc3 = {0,0,0,0};
        #pragma unroll
        for (int db = 0; db < 16; ++db) {          // groups of 4 d
            const int x = db & 7;
            const float* ktb = kt + db * 4 * KT + ((kg ^ x) << 2);
            const float* qsb = qs + db * 4 * QT + (qg << 2);
            #pragma unroll
            for (int dd2 = 0; dd2 < 4; ++dd2) {
                float4 kv = *(const float4*)(ktb + dd2 * KT);  // 4 k cols @ d
                float4 qv = *(const float4*)(qsb + dd2 * QT);  // 4 q rows @ d
                acc0.x = fmaf(qv.x, kv.x, acc0.x); acc0.y = fmaf(qv.x, kv.y, acc0.y);
                acc0.z = fmaf(qv.x, kv.z, acc0.z); acc0.w = fmaf(qv.x, kv.w, acc0.w);
                acc1.x = fmaf(qv.y, kv.x, acc1.x); acc1.y = fmaf(qv.y, kv.y, acc1.y);
                acc1.z = fmaf(qv.y, kv.z, acc1.z); acc1.w = fmaf(qv.y, kv.w, acc1.w);
                acc2.x = fmaf(qv.z, kv.x, acc2.x); acc2.y = fmaf(qv.z, kv.y, acc2.y);
                acc2.z = fmaf(qv.z, kv.z, acc2.z); acc2.w = fmaf(qv.z, kv.w, acc2.w);
                acc3.x = fmaf(qv.w, kv.x, acc3.x); acc3.y = fmaf(qv.w, kv.y, acc3.y);
                acc3.z = fmaf(qv.w, kv.z, acc3.z); acc3.w = fmaf(qv.w, kv.w, acc3.w);
            }
        }
        __syncthreads();   // reads done before next staging overwrites kt

        // fused epilogue: clip -> mask -> decay -> store to sc
        float4 accs[4] = {acc0, acc1, acc2, acc3};
        #pragma unroll
        for (int i = 0; i < 4; ++i) {
            float4 s = accs[i];
            s.x = fminf(fmaxf(s.x, 1e-9f), 1e9f);
            s.y = fminf(fmaxf(s.y, 1e-9f), 1e9f);
            s.z = fminf(fmaxf(s.z, 1e-9f), 1e9f);
            s.w = fminf(fmaxf(s.w, 1e-9f), 1e9f);
            s.x = msk[i].x ? s.x : -1e9f;
            s.y = msk[i].y ? s.y : -1e9f;
            s.z = msk[i].z ? s.z : -1e9f;
            s.w = msk[i].w ? s.w : -1e9f;
            s.x *= dec[i].x; s.y *= dec[i].y; s.z *= dec[i].z; s.w *= dec[i].w;
            *(float4*)&sc[(size_t)(qg * 4 + i) * Sc + col0] = s;
        }
    }
    __syncthreads();

    // ================= softmax per row + write p_attn =================
    {
        const int wid  = t >> 5;
        const int lane = t & 31;
        for (int r = wid; r < QT; r += 8) {
            float* row = &sc[r * Sc];
            float mx = -3.4e38f;
            #pragma unroll 4
            for (int k = lane; k < Sc; k += 32) mx = fmaxf(mx, row[k]);
            #pragma unroll
            for (int o = 16; o; o >>= 1) mx = fmaxf(mx, __shfl_xor_sync(0xffffffffu, mx, o));

            float sum = 0.f;
            #pragma unroll 4
            for (int k = lane; k < Sc; k += 32) {
                float e = __expf(row[k] - mx);
                row[k] = e;
                sum += e;
            }
            #pragma unroll
            for (int o = 16; o; o >>= 1) sum += __shfl_xor_sync(0xffffffffu, sum, o);
            float inv = 1.f / sum;

            float* gp = out_p + ((size_t)bh * Sc + q0 + r) * Sc;
            #pragma unroll 4
            for (int k = lane * 4; k < Sc; k += 128) {
                float4 e = *(float4*)&row[k];
                e.x *= inv; e.y *= inv; e.z *= inv; e.w *= inv;
                *(float4*)&row[k] = e;
                *(float4*)&gp[k]  = e;
            }
        }
    }

    // ================= P @ V =================
    // threads split in 2 halves over kk; each thread: 2 q-rows x 4 d-cols.
    {
        const int half = t >> 7;
        const int tt   = t & 127;
        const int r0   = (tt >> 4) * 2;
        const int r1   = r0 + 1;
        const int dg4  = (tt & 15) * 4;

        float4 accA = {0,0,0,0}, accB = {0,0,0,0};

        for (int tile = 0; tile < Sc / KT; ++tile) {
            __syncthreads();   // prev consumers done (also fences softmax on tile 0)
            const float4* src = (const float4*)(Vp + (size_t)tile * KT * Dc);
            #pragma unroll
            for (int r = 0; r < 16; ++r) {
                int idx = t + r * NT;
                ((float4*)kt)[idx] = src[idx];   // V tile [256][64] row-major
            }
            __syncthreads();

            const float* pa = &sc[(size_t)r0 * Sc + tile * KT + half * 128];
            const float* pb = &sc[(size_t)r1 * Sc + tile * KT + half * 128];
            const float* vb = kt + (half * 128) * Dc + dg4;
            #pragma unroll 8
            for (int m = 0; m < 64; ++m) {
                float2 p0 = *(const float2*)(pa + 2 * m);
                float2 p1 = *(const float2*)(pb + 2 * m);
                float4 v0 = *(const float4*)(vb + (2 * m) * Dc);
                float4 v1 = *(const float4*)(vb + (2 * m + 1) * Dc);
                accA.x = fmaf(p0.x, v0.x, accA.x); accA.y = fmaf(p0.x, v0.y, accA.y);
                accA.z = fmaf(p0.x, v0.z, accA.z); accA.w = fmaf(p0.x, v0.w, accA.w);
                accA.x = fmaf(p0.y, v1.x, accA.x); accA.y = fmaf(p0.y, v1.y, accA.y);
                accA.z = fmaf(p0.y, v1.z, accA.z); accA.w = fmaf(p0.y, v1.w, accA.w);
                accB.x = fmaf(p1.x, v0.x, accB.x); accB.y = fmaf(p1.x, v0.y, accB.y);
                accB.z = fmaf(p1.x, v0.z, accB.z); accB.w = fmaf(p1.x, v0.w, accB.w);
                accB.x = fmaf(p1.y, v1.x, accB.x); accB.y = fmaf(p1.y, v1.y, accB.y);
                accB.z = fmaf(p1.y, v1.z, accB.z); accB.w = fmaf(p1.y, v1.w, accB.w);
            }
        }

        // reduce the two kk-halves through qs (16x64 floats)
        __syncthreads();
        if (half == 0) {
            *(float4*)&qs[r0 * 64 + dg4] = accA;
            *(float4*)&qs[r1 * 64 + dg4] = accB;
        }
        __syncthreads();
        if (half == 1) {
            float4 oA = *(const float4*)&qs[r0 * 64 + dg4];
            float4 oB = *(const float4*)&qs[r1 * 64 + dg4];
            accA.x += oA.x; accA.y += oA.y; accA.z += oA.z; accA.w += oA.w;
            accB.x += oB.x; accB.y += oB.y; accB.z += oB.z; accB.w += oB.w;
            *(float4*)(out_o + ((size_t)bh * Sc + q0 + r0) * Dc + dg4) = accA;
            *(float4*)(out_o + ((size_t)bh * Sc + q0 + r1) * Dc + dg4) = accB;
        }
    }
}

extern "C" void kernel_launch(void* const* d_in, const int* in_sizes, int n_in,
                              void* d_out, int out_size)
{
    const float* Q     = (const float*)d_in[0];
    const float* K     = (const float*)d_in[1];
    const float* V     = (const float*)d_in[2];
    const int*   mask  = (const int*)d_in[3];
    const float* decay = (const float*)d_in[4];

    float* out_o = (float*)d_out;                                 // [B,H,S,D]
    float* out_p = (float*)d_out + (size_t)Bc * Hc * Sc * Dc;     // [B,H,S,S]

    cudaFuncSetAttribute(attn_kernel, cudaFuncAttributeMaxDynamicSharedMemorySize,
                         (int)SMEM_BYTES);

    int blocks = Bc * Hc * (Sc / QT);   // 2048
    attn_kernel<<<blocks, NT, SMEM_BYTES>>>(Q, K, V, mask, decay, out_o, out_p);
}

// round 5
// speedup vs baseline: 4.7205x; 2.0429x over previous
#include <cuda_runtime.h>
#include <cuda_bf16.h>
#include <cstdint>

constexpr int BH = 16, S = 2048, D = 64;

__device__ float g_sums[BH * S];

// ---------------- helpers ----------------
__device__ __forceinline__ uint32_t smem_u32(const void* p) {
    uint32_t a;
    asm("{ .reg .u64 t; cvta.to.shared.u64 t, %1; cvt.u32.u64 %0, t; }" : "=r"(a) : "l"(p));
    return a;
}
__device__ __forceinline__ uint32_t pk(float a, float b) {
    __nv_bfloat162 t = __floats2bfloat162_rn(a, b);
    return *reinterpret_cast<uint32_t*>(&t);
}
__device__ __forceinline__ float hi_bf(float x) {
    return __bfloat162float(__float2bfloat16_rn(x));
}
__device__ __forceinline__ uint32_t sw128(uint32_t b) { return b ^ ((b >> 3) & 0x70); }  // 128B rows
__device__ __forceinline__ uint32_t sw256(uint32_t b) { return b ^ ((b >> 4) & 0x70); }  // 256B rows

__device__ __forceinline__ void ldsm4(uint32_t a, uint32_t r[4]) {
    asm volatile("ldmatrix.sync.aligned.m8n8.x4.shared.b16 {%0,%1,%2,%3}, [%4];"
                 : "=r"(r[0]), "=r"(r[1]), "=r"(r[2]), "=r"(r[3]) : "r"(a));
}
__device__ __forceinline__ void ldsm4t(uint32_t a, uint32_t r[4]) {
    asm volatile("ldmatrix.sync.aligned.m8n8.x4.trans.shared.b16 {%0,%1,%2,%3}, [%4];"
                 : "=r"(r[0]), "=r"(r[1]), "=r"(r[2]), "=r"(r[3]) : "r"(a));
}
__device__ __forceinline__ void mma16816(float c[4], const uint32_t a[4], uint32_t b0, uint32_t b1) {
    asm volatile(
        "mma.sync.aligned.m16n8k16.row.col.f32.bf16.bf16.f32 "
        "{%0,%1,%2,%3}, {%4,%5,%6,%7}, {%8,%9}, {%0,%1,%2,%3};"
        : "+f"(c[0]), "+f"(c[1]), "+f"(c[2]), "+f"(c[3])
        : "r"(a[0]), "r"(a[1]), "r"(a[2]), "r"(a[3]), "r"(b0), "r"(b1));
}

// ---------------- kernel A: e = exp(clip/mask/decay(QK^T)), row sums ----------------
// smem: Qhi[64][64]bf16, Qlo, Khi[128][64]bf16, Klo, sumbuf[64]f32
constexpr int QHI = 0, QLO = 8192, KHI = 16384, KLO = 32768, SUMO = 49152;
constexpr size_t SMEM_A = 49152 + 256;

__global__ void __launch_bounds__(256, 2)
qk_kernel(const float* __restrict__ Q, const float* __restrict__ K,
          const int* __restrict__ mask, const float* __restrict__ decay,
          float* __restrict__ e_out)
{
    extern __shared__ char sm[];
    const uint32_t sb = smem_u32(sm);
    const int t = threadIdx.x, wid = t >> 5, lane = t & 31;
    const int bid = blockIdx.x, bh = bid >> 5, q0 = (bid & 31) * 64, b = bh >> 3;

    // stage Q tile (pre-scaled 1/8) -> hi/lo bf16, swizzled 128B rows
    {
        const float4* Qp = (const float4*)(Q + ((size_t)bh * S + q0) * D);
        #pragma unroll
        for (int i = 0; i < 4; ++i) {
            int idx = t + i * 256, r = idx >> 4, c4 = (idx & 15) * 4;
            float4 v = Qp[idx];
            float x0 = v.x * 0.125f, x1 = v.y * 0.125f, x2 = v.z * 0.125f, x3 = v.w * 0.125f;
            float h0 = hi_bf(x0), h1 = hi_bf(x1), h2 = hi_bf(x2), h3 = hi_bf(x3);
            uint32_t o = sw128((uint32_t)(r * 128 + c4 * 2));
            *(uint2*)(sm + QHI + o) = make_uint2(pk(h0, h1), pk(h2, h3));
            *(uint2*)(sm + QLO + o) = make_uint2(pk(x0 - h0, x1 - h1), pk(x2 - h2, x3 - h3));
        }
    }

    const int wm = wid & 3;        // m16 block
    const int wn = wid >> 2;       // 64-col half of the 128-col tile
    const int r0 = wm * 16 + (lane >> 2), r1 = r0 + 8;
    const size_t gq0 = (size_t)bh * S + q0;
    const float* drow0 = decay + (gq0 + r0) * S;
    const float* drow1 = decay + (gq0 + r1) * S;
    const int*   mrow0 = mask + ((size_t)b * S + q0 + r0) * S;
    const int*   mrow1 = mask + ((size_t)b * S + q0 + r1) * S;
    float*       erow0 = e_out + (gq0 + r0) * S;
    float*       erow1 = e_out + (gq0 + r1) * S;
    float sum0 = 0.f, sum1 = 0.f;

    // fragment smem addresses (lane-dependent parts precomputed)
    const uint32_t a_off = sw128(0) * 0;  // dummy
    for (int it = 0; it < 16; ++it) {
        __syncthreads();
        // stage K tile [128 kv rows][64 d] -> hi/lo
        {
            const float4* Kp = (const float4*)(K + ((size_t)bh * S + it * 128) * D);
            #pragma unroll
            for (int i = 0; i < 8; ++i) {
                int idx = t + i * 256, r = idx >> 4, c4 = (idx & 15) * 4;
                float4 v = Kp[idx];
                float h0 = hi_bf(v.x), h1 = hi_bf(v.y), h2 = hi_bf(v.z), h3 = hi_bf(v.w);
                uint32_t o = sw128((uint32_t)(r * 128 + c4 * 2));
                *(uint2*)(sm + KHI + o) = make_uint2(pk(h0, h1), pk(h2, h3));
                *(uint2*)(sm + KLO + o) = make_uint2(pk(v.x - h0, v.y - h1), pk(v.z - h2, v.w - h3));
            }
        }
        __syncthreads();

        float acc[8][4];
        #pragma unroll
        for (int n = 0; n < 8; ++n)
            #pragma unroll
            for (int j = 0; j < 4; ++j) acc[n][j] = 0.f;

        #pragma unroll
        for (int kc4 = 0; kc4 < 4; ++kc4) {
            const int kc = kc4 * 16;
            const uint32_t arow = (uint32_t)((wm * 16 + (lane & 15)) * 128 +
                                             (kc + ((lane >> 4) & 1) * 8) * 2);
            uint32_t ah[4], al[4];
            ldsm4(sb + QHI + sw128(arow), ah);
            // B address pattern for 2 n-tiles via x4
            #pragma unroll
            for (int p = 0; p < 4; ++p) {
                uint32_t brow = (uint32_t)((wn * 64 + p * 16 + (lane & 7) + (lane >> 4) * 8) * 128 +
                                           (kc + ((lane >> 3) & 1) * 8) * 2);
                uint32_t bo = sw128(brow);
                uint32_t bb[4];
                ldsm4(sb + KHI + bo, bb);
                mma16816(acc[2 * p], ah, bb[0], bb[1]);
                mma16816(acc[2 * p + 1], ah, bb[2], bb[3]);
                ldsm4(sb + KLO + bo, bb);
                mma16816(acc[2 * p], ah, bb[0], bb[1]);
                mma16816(acc[2 * p + 1], ah, bb[2], bb[3]);
            }
            ldsm4(sb + QLO + sw128(arow), al);
            #pragma unroll
            for (int p = 0; p < 4; ++p) {
                uint32_t brow = (uint32_t)((wn * 64 + p * 16 + (lane & 7) + (lane >> 4) * 8) * 128 +
                                           (kc + ((lane >> 3) & 1) * 8) * 2);
                uint32_t bb[4];
                ldsm4(sb + KHI + sw128(brow), bb);
                mma16816(acc[2 * p], al, bb[0], bb[1]);
                mma16816(acc[2 * p + 1], al, bb[2], bb[3]);
            }
        }

        // epilogue: clip/mask/decay/exp, store e, accumulate row sums
        const int cb0 = it * 128 + wn * 64 + (lane & 3) * 2;
        #pragma unroll
        for (int nt = 0; nt < 8; ++nt) {
            const int c = cb0 + nt * 8;
            float2 d0 = *(const float2*)(drow0 + c);
            float2 d1 = *(const float2*)(drow1 + c);
            int2   m0 = *(const int2*)(mrow0 + c);
            int2   m1 = *(const int2*)(mrow1 + c);
            float s00 = fminf(fmaxf(acc[nt][0], 1e-9f), 1e9f);
            float s01 = fminf(fmaxf(acc[nt][1], 1e-9f), 1e9f);
            float s10 = fminf(fmaxf(acc[nt][2], 1e-9f), 1e9f);
            float s11 = fminf(fmaxf(acc[nt][3], 1e-9f), 1e9f);
            s00 = m0.x ? s00 : -1e9f;  s01 = m0.y ? s01 : -1e9f;
            s10 = m1.x ? s10 : -1e9f;  s11 = m1.y ? s11 : -1e9f;
            float e00 = __expf(s00 * d0.x), e01 = __expf(s01 * d0.y);
            float e10 = __expf(s10 * d1.x), e11 = __expf(s11 * d1.y);
            sum0 += e00 + e01;
            sum1 += e10 + e11;
            *(float2*)(erow0 + c) = make_float2(e00, e01);
            *(float2*)(erow1 + c) = make_float2(e10, e11);
        }
    }

    // reduce row sums: quad (same row) then across the two n-half warps
    #pragma unroll
    for (int o = 1; o <= 2; o <<= 1) {
        sum0 += __shfl_xor_sync(0xffffffffu, sum0, o);
        sum1 += __shfl_xor_sync(0xffffffffu, sum1, o);
    }
    float* sbuf = (float*)(sm + SUMO);
    __syncthreads();
    if (wn == 0 && (lane & 3) == 0) {
        sbuf[wm * 16 + (lane >> 2)]     = sum0;
        sbuf[wm * 16 + 8 + (lane >> 2)] = sum1;
    }
    __syncthreads();
    if (wn == 1 && (lane & 3) == 0) {
        g_sums[gq0 + r0] = sbuf[wm * 16 + (lane >> 2)] + sum0;
        g_sums[gq0 + r1] = sbuf[wm * 16 + 8 + (lane >> 2)] + sum1;
    }
    (void)a_off;
}

// ---------------- kernel B: p = e*inv (in place), O = (e@V)*inv ----------------
// smem: Phi[64][128]bf16, Plo, Vhi[128][64]bf16, Vlo, inv[64]f32
constexpr int PHI = 0, PLO = 16384, VHI = 32768, VLO = 49152, INVO = 65536;
constexpr size_t SMEM_B = 65536 + 256;

__global__ void __launch_bounds__(256, 2)
pv_kernel(const float* __restrict__ V, float* __restrict__ p, float* __restrict__ out_o)
{
    extern __shared__ char sm[];
    const uint32_t sb = smem_u32(sm);
    const int t = threadIdx.x, wid = t >> 5, lane = t & 31;
    const int bid = blockIdx.x, bh = bid >> 5, q0 = (bid & 31) * 64;

    float* invs = (float*)(sm + INVO);
    if (t < 64) invs[t] = 1.f / g_sums[(size_t)bh * S + q0 + t];

    const int wm = wid & 3;      // m16 block
    const int wn = wid >> 2;     // 32-col half of D=64
    float acc[4][4];
    #pragma unroll
    for (int n = 0; n < 4; ++n)
        #pragma unroll
        for (int j = 0; j < 4; ++j) acc[n][j] = 0.f;

    __syncthreads();

    for (int it = 0; it < 16; ++it) {
        __syncthreads();
        // stage P: read e, write p = e*inv in place, split hi/lo (256B rows)
        {
            float* ebase = p + ((size_t)bh * S + q0) * S + it * 128;
            #pragma unroll
            for (int i = 0; i < 8; ++i) {
                int idx = t + i * 256, r = idx >> 5, c4 = (idx & 31) * 4;
                float* ep = ebase + (size_t)r * S + c4;
                float4 ev = *(const float4*)ep;
                float iv = invs[r];
                *(float4*)ep = make_float4(ev.x * iv, ev.y * iv, ev.z * iv, ev.w * iv);
                float h0 = hi_bf(ev.x), h1 = hi_bf(ev.y), h2 = hi_bf(ev.z), h3 = hi_bf(ev.w);
                uint32_t o = sw256((uint32_t)(r * 256 + c4 * 2));
                *(uint2*)(sm + PHI + o) = make_uint2(pk(h0, h1), pk(h2, h3));
                *(uint2*)(sm + PLO + o) = make_uint2(pk(ev.x - h0, ev.y - h1), pk(ev.z - h2, ev.w - h3));
            }
        }
        // stage V tile [128 kv rows][64 d] hi/lo (128B rows)
        {
            const float4* Vp = (const float4*)(V + ((size_t)bh * S + it * 128) * D);
            #pragma unroll
            for (int i = 0; i < 8; ++i) {
                int idx = t + i * 256, r = idx >> 4, d4 = (idx & 15) * 4;
                float4 v = Vp[idx];
                float h0 = hi_bf(v.x), h1 = hi_bf(v.y), h2 = hi_bf(v.z), h3 = hi_bf(v.w);
                uint32_t o = sw128((uint32_t)(r * 128 + d4 * 2));
                *(uint2*)(sm + VHI + o) = make_uint2(pk(h0, h1), pk(h2, h3));
                *(uint2*)(sm + VLO + o) = make_uint2(pk(v.x - h0, v.y - h1), pk(v.z - h2, v.w - h3));
            }
        }
        __syncthreads();

        #pragma unroll
        for (int kc8 = 0; kc8 < 8; ++kc8) {
            const int kc = kc8 * 16;
            const uint32_t arow = (uint32_t)((wm * 16 + (lane & 15)) * 256 +
                                             (kc + ((lane >> 4) & 1) * 8) * 2);
            uint32_t ah[4], al[4];
            ldsm4(sb + PHI + sw256(arow), ah);
            #pragma unroll
            for (int p2 = 0; p2 < 2; ++p2) {
                uint32_t brow = (uint32_t)((kc + (lane & 7) + ((lane >> 3) & 1) * 8) * 128 +
                                           (wn * 32 + p2 * 16 + (lane >> 4) * 8) * 2);
                uint32_t bo = sw128(brow);
                uint32_t bb[4];
                ldsm4t(sb + VHI + bo, bb);
                mma16816(acc[2 * p2], ah, bb[0], bb[1]);
                mma16816(acc[2 * p2 + 1], ah, bb[2], bb[3]);
                ldsm4t(sb + VLO + bo, bb);
                mma16816(acc[2 * p2], ah, bb[0], bb[1]);
                mma16816(acc[2 * p2 + 1], ah, bb[2], bb[3]);
            }
            ldsm4(sb + PLO + sw256(arow), al);
            #pragma unroll
            for (int p2 = 0; p2 < 2; ++p2) {
                uint32_t brow = (uint32_t)((kc + (lane & 7) + ((lane >> 3) & 1) * 8) * 128 +
                                           (wn * 32 + p2 * 16 + (lane >> 4) * 8) * 2);
                uint32_t bb[4];
                ldsm4t(sb + VHI + sw128(brow), bb);
                mma16816(acc[2 * p2], al, bb[0], bb[1]);
                mma16816(acc[2 * p2 + 1], al, bb[2], bb[3]);
            }
        }
    }

    // epilogue: O = acc * inv
    const int r0 = wm * 16 + (lane >> 2), r1 = r0 + 8;
    const float iv0 = invs[r0], iv1 = invs[r1];
    float* ob0 = out_o + ((size_t)bh * S + q0 + r0) * D;
    float* ob1 = out_o + ((size_t)bh * S + q0 + r1) * D;
    #pragma unroll
    for (int nt = 0; nt < 4; ++nt) {
        const int c = wn * 32 + nt * 8 + (lane & 3) * 2;
        *(float2*)(ob0 + c) = make_float2(acc[nt][0] * iv0, acc[nt][1] * iv0);
        *(float2*)(ob1 + c) = make_float2(acc[nt][2] * iv1, acc[nt][3] * iv1);
    }
}

extern "C" void kernel_launch(void* const* d_in, const int* in_sizes, int n_in,
                              void* d_out, int out_size)
{
    const float* Q     = (const float*)d_in[0];
    const float* K     = (const float*)d_in[1];
    const float* V     = (const float*)d_in[2];
    const int*   mask  = (const int*)d_in[3];
    const float* decay = (const float*)d_in[4];

    float* out_o = (float*)d_out;
    float* out_p = (float*)d_out + (size_t)BH * S * D;

    cudaFuncSetAttribute(qk_kernel, cudaFuncAttributeMaxDynamicSharedMemorySize, (int)SMEM_A);
    cudaFuncSetAttribute(pv_kernel, cudaFuncAttributeMaxDynamicSharedMemorySize, (int)SMEM_B);

    int blocks = BH * (S / 64);   // 512
    qk_kernel<<<blocks, 256, SMEM_A>>>(Q, K, mask, decay, out_p);
    pv_kernel<<<blocks, 256, SMEM_B>>>(V, out_p, out_o);
}

// round 6
// speedup vs baseline: 5.3610x; 1.1357x over previous
#include <cuda_runtime.h>
#include <cuda_bf16.h>
#include <cstdint>

constexpr int BH = 16, S = 2048, D = 64;

__device__ float g_sums[BH * S];

// ---------------- helpers ----------------
__device__ __forceinline__ uint32_t smem_u32(const void* p) {
    uint32_t a;
    asm("{ .reg .u64 t; cvta.to.shared.u64 t, %1; cvt.u32.u64 %0, t; }" : "=r"(a) : "l"(p));
    return a;
}
__device__ __forceinline__ uint32_t pk(float a, float b) {
    __nv_bfloat162 t = __floats2bfloat162_rn(a, b);
    return *reinterpret_cast<uint32_t*>(&t);
}
__device__ __forceinline__ float hi_bf(float x) {
    return __bfloat162float(__float2bfloat16_rn(x));
}
__device__ __forceinline__ uint32_t sw128(uint32_t b) { return b ^ ((b >> 3) & 0x70); }

__device__ __forceinline__ void ldsm4(uint32_t a, uint32_t r[4]) {
    asm volatile("ldmatrix.sync.aligned.m8n8.x4.shared.b16 {%0,%1,%2,%3}, [%4];"
                 : "=r"(r[0]), "=r"(r[1]), "=r"(r[2]), "=r"(r[3]) : "r"(a));
}
__device__ __forceinline__ void ldsm4t(uint32_t a, uint32_t r[4]) {
    asm volatile("ldmatrix.sync.aligned.m8n8.x4.trans.shared.b16 {%0,%1,%2,%3}, [%4];"
                 : "=r"(r[0]), "=r"(r[1]), "=r"(r[2]), "=r"(r[3]) : "r"(a));
}
__device__ __forceinline__ void mma16816(float c[4], const uint32_t a[4], uint32_t b0, uint32_t b1) {
    asm volatile(
        "mma.sync.aligned.m16n8k16.row.col.f32.bf16.bf16.f32 "
        "{%0,%1,%2,%3}, {%4,%5,%6,%7}, {%8,%9}, {%0,%1,%2,%3};"
        : "+f"(c[0]), "+f"(c[1]), "+f"(c[2]), "+f"(c[3])
        : "r"(a[0]), "r"(a[1]), "r"(a[2]), "r"(a[3]), "r"(b0), "r"(b1));
}

// smem map (bytes): Qhi 8K, Qlo 8K, Khi 16K, Klo 16K, Vhi 16K, Vlo 16K, sums 256
constexpr int QHI = 0, QLO = 8192, KHI = 16384, KLO = 32768,
              VHI = 49152, VLO = 65536, SUMO = 81920, OBUF = 16384;
constexpr size_t SMEM_F = 82432;

// ============ fused: e = exp(clip/mask/decay(QK^T)) -> p region, O = (e@V)*inv ============
__global__ void __launch_bounds__(256, 2)
fused_kernel(const float* __restrict__ Q, const float* __restrict__ K,
             const float* __restrict__ V, const int* __restrict__ mask,
             const float* __restrict__ decay, float* __restrict__ e_out,
             float* __restrict__ out_o)
{
    extern __shared__ char sm[];
    const uint32_t sb = smem_u32(sm);
    const int t = threadIdx.x, wid = t >> 5, lane = t & 31;
    const int bid = blockIdx.x, bh = bid >> 5, q0 = (bid & 31) * 64, b = bh >> 3;

    // stage Q tile (pre-scaled 1/8) -> hi/lo bf16
    {
        const float4* Qp = (const float4*)(Q + ((size_t)bh * S + q0) * D);
        #pragma unroll
        for (int i = 0; i < 4; ++i) {
            int idx = t + i * 256, r = idx >> 4, c4 = (idx & 15) * 4;
            float4 v = Qp[idx];
            float x0 = v.x * 0.125f, x1 = v.y * 0.125f, x2 = v.z * 0.125f, x3 = v.w * 0.125f;
            float h0 = hi_bf(x0), h1 = hi_bf(x1), h2 = hi_bf(x2), h3 = hi_bf(x3);
            uint32_t o = sw128((uint32_t)(r * 128 + c4 * 2));
            *(uint2*)(sm + QHI + o) = make_uint2(pk(h0, h1), pk(h2, h3));
            *(uint2*)(sm + QLO + o) = make_uint2(pk(x0 - h0, x1 - h1), pk(x2 - h2, x3 - h3));
        }
    }

    const int wm = wid & 3;        // m16 block (q rows)
    const int wn = wid >> 2;       // 64-col half of the 128-col kv tile
    const int r0 = wm * 16 + (lane >> 2), r1 = r0 + 8;
    const size_t gq0 = (size_t)bh * S + q0;
    const float* drow0 = decay + (gq0 + r0) * S;
    const float* drow1 = decay + (gq0 + r1) * S;
    const int*   mrow0 = mask + ((size_t)b * S + q0 + r0) * S;
    const int*   mrow1 = mask + ((size_t)b * S + q0 + r1) * S;
    float*       erow0 = e_out + (gq0 + r0) * S;
    float*       erow1 = e_out + (gq0 + r1) * S;
    float sum0 = 0.f, sum1 = 0.f;

    float oacc[8][4];
    #pragma unroll
    for (int n = 0; n < 8; ++n)
        #pragma unroll
        for (int j = 0; j < 4; ++j) oacc[n][j] = 0.f;

    for (int it = 0; it < 16; ++it) {
        __syncthreads();
        // stage K,V tiles [128 kv][64 d] -> hi/lo bf16
        {
            const float4* Kp = (const float4*)(K + ((size_t)bh * S + it * 128) * D);
            const float4* Vp = (const float4*)(V + ((size_t)bh * S + it * 128) * D);
            #pragma unroll
            for (int i = 0; i < 8; ++i) {
                int idx = t + i * 256, r = idx >> 4, c4 = (idx & 15) * 4;
                uint32_t o = sw128((uint32_t)(r * 128 + c4 * 2));
                float4 v = Kp[idx];
                float h0 = hi_bf(v.x), h1 = hi_bf(v.y), h2 = hi_bf(v.z), h3 = hi_bf(v.w);
                *(uint2*)(sm + KHI + o) = make_uint2(pk(h0, h1), pk(h2, h3));
                *(uint2*)(sm + KLO + o) = make_uint2(pk(v.x - h0, v.y - h1), pk(v.z - h2, v.w - h3));
                float4 w = Vp[idx];
                float g0 = hi_bf(w.x), g1 = hi_bf(w.y), g2 = hi_bf(w.z), g3 = hi_bf(w.w);
                *(uint2*)(sm + VHI + o) = make_uint2(pk(g0, g1), pk(g2, g3));
                *(uint2*)(sm + VLO + o) = make_uint2(pk(w.x - g0, w.y - g1), pk(w.z - g2, w.w - g3));
            }
        }
        __syncthreads();

        // ---------------- S = QK^T (3-split) ----------------
        float acc[8][4];
        #pragma unroll
        for (int n = 0; n < 8; ++n)
            #pragma unroll
            for (int j = 0; j < 4; ++j) acc[n][j] = 0.f;

        #pragma unroll
        for (int kc4 = 0; kc4 < 4; ++kc4) {
            const int kc = kc4 * 16;
            const uint32_t arow = (uint32_t)((wm * 16 + (lane & 15)) * 128 +
                                             (kc + ((lane >> 4) & 1) * 8) * 2);
            uint32_t ah[4], al[4];
            ldsm4(sb + QHI + sw128(arow), ah);
            #pragma unroll
            for (int p = 0; p < 4; ++p) {
                uint32_t brow = (uint32_t)((wn * 64 + p * 16 + (lane & 7) + (lane >> 4) * 8) * 128 +
                                           (kc + ((lane >> 3) & 1) * 8) * 2);
                uint32_t bo = sw128(brow);
                uint32_t bb[4];
                ldsm4(sb + KHI + bo, bb);
                mma16816(acc[2 * p], ah, bb[0], bb[1]);
                mma16816(acc[2 * p + 1], ah, bb[2], bb[3]);
                ldsm4(sb + KLO + bo, bb);
                mma16816(acc[2 * p], ah, bb[0], bb[1]);
                mma16816(acc[2 * p + 1], ah, bb[2], bb[3]);
            }
            ldsm4(sb + QLO + sw128(arow), al);
            #pragma unroll
            for (int p = 0; p < 4; ++p) {
                uint32_t brow = (uint32_t)((wn * 64 + p * 16 + (lane & 7) + (lane >> 4) * 8) * 128 +
                                           (kc + ((lane >> 3) & 1) * 8) * 2);
                uint32_t bb[4];
                ldsm4(sb + KHI + sw128(brow), bb);
                mma16816(acc[2 * p], al, bb[0], bb[1]);
                mma16816(acc[2 * p + 1], al, bb[2], bb[3]);
            }
        }

        // ---------------- epilogue: clip/mask/decay/exp, store e, keep e in acc ----------------
        const int cb0 = it * 128 + wn * 64 + (lane & 3) * 2;
        #pragma unroll
        for (int nt = 0; nt < 8; ++nt) {
            const int c = cb0 + nt * 8;
            float2 d0 = *(const float2*)(drow0 + c);
            float2 d1 = *(const float2*)(drow1 + c);
            int2   m0 = *(const int2*)(mrow0 + c);
            int2   m1 = *(const int2*)(mrow1 + c);
            float s00 = fminf(fmaxf(acc[nt][0], 1e-9f), 1e9f);
            float s01 = fminf(fmaxf(acc[nt][1], 1e-9f), 1e9f);
            float s10 = fminf(fmaxf(acc[nt][2], 1e-9f), 1e9f);
            float s11 = fminf(fmaxf(acc[nt][3], 1e-9f), 1e9f);
            s00 = m0.x ? s00 : -1e9f;  s01 = m0.y ? s01 : -1e9f;
            s10 = m1.x ? s10 : -1e9f;  s11 = m1.y ? s11 : -1e9f;
            float e00 = __expf(s00 * d0.x), e01 = __expf(s01 * d0.y);
            float e10 = __expf(s10 * d1.x), e11 = __expf(s11 * d1.y);
            sum0 += e00 + e01;
            sum1 += e10 + e11;
            *(float2*)(erow0 + c) = make_float2(e00, e01);
            *(float2*)(erow1 + c) = make_float2(e10, e11);
            acc[nt][0] = e00; acc[nt][1] = e01; acc[nt][2] = e10; acc[nt][3] = e11;
        }

        // ---------------- PV: O += e @ V  (A recycled from accumulators) ----------------
        #pragma unroll
        for (int kc = 0; kc < 4; ++kc) {
            // C-fragment of S == A-fragment of PV (same lane mapping)
            float h00 = hi_bf(acc[2*kc][0]),   h01 = hi_bf(acc[2*kc][1]);
            float h02 = hi_bf(acc[2*kc][2]),   h03 = hi_bf(acc[2*kc][3]);
            float h10 = hi_bf(acc[2*kc+1][0]), h11 = hi_bf(acc[2*kc+1][1]);
            float h12 = hi_bf(acc[2*kc+1][2]), h13 = hi_bf(acc[2*kc+1][3]);
            uint32_t ah[4] = { pk(h00, h01), pk(h02, h03), pk(h10, h11), pk(h12, h13) };
            uint32_t al[4] = { pk(acc[2*kc][0] - h00,   acc[2*kc][1] - h01),
                               pk(acc[2*kc][2] - h02,   acc[2*kc][3] - h03),
                               pk(acc[2*kc+1][0] - h10, acc[2*kc+1][1] - h11),
                               pk(acc[2*kc+1][2] - h12, acc[2*kc+1][3] - h13) };
            #pragma unroll
            for (int p2 = 0; p2 < 4; ++p2) {
                uint32_t brow = (uint32_t)((wn * 64 + kc * 16 + (lane & 7) + ((lane >> 3) & 1) * 8) * 128 +
                                           (p2 * 16 + (lane >> 4) * 8) * 2);
                uint32_t bo = sw128(brow);
                uint32_t bb[4];
                ldsm4t(sb + VHI + bo, bb);
                mma16816(oacc[2 * p2],     ah, bb[0], bb[1]);
                mma16816(oacc[2 * p2 + 1], ah, bb[2], bb[3]);
                mma16816(oacc[2 * p2],     al, bb[0], bb[1]);
                mma16816(oacc[2 * p2 + 1], al, bb[2], bb[3]);
                ldsm4t(sb + VLO + bo, bb);
                mma16816(oacc[2 * p2],     ah, bb[0], bb[1]);
                mma16816(oacc[2 * p2 + 1], ah, bb[2], bb[3]);
            }
        }
    }

    // ---------------- row sums -> inv, g_sums ----------------
    #pragma unroll
    for (int o = 1; o <= 2; o <<= 1) {
        sum0 += __shfl_xor_sync(0xffffffffu, sum0, o);
        sum1 += __shfl_xor_sync(0xffffffffu, sum1, o);
    }
    float* sbuf = (float*)(sm + SUMO);
    __syncthreads();
    if (wn == 0 && (lane & 3) == 0) { sbuf[r0] = sum0; sbuf[r1] = sum1; }
    __syncthreads();
    if (wn == 1 && (lane & 3) == 0) {
        float t0 = sbuf[r0] + sum0, t1 = sbuf[r1] + sum1;
        sbuf[r0] = t0; sbuf[r1] = t1;
        g_sums[gq0 + r0] = t0;
        g_sums[gq0 + r1] = t1;
    }
    __syncthreads();

    // ---------------- O: reduce across the two kv-half warps, scale, store ----------------
    float* ob = (float*)(sm + OBUF);   // [64][64], reuses K/V staging space
    const int cc = (lane & 3) * 2;
    if (wn == 0) {
        #pragma unroll
        for (int nt = 0; nt < 8; ++nt) {
            ob[r0 * 64 + nt * 8 + cc]     = oacc[nt][0];
            ob[r0 * 64 + nt * 8 + cc + 1] = oacc[nt][1];
            ob[r1 * 64 + nt * 8 + cc]     = oacc[nt][2];
            ob[r1 * 64 + nt * 8 + cc + 1] = oacc[nt][3];
        }
    }
    __syncthreads();
    if (wn == 1) {
        float iv0 = 1.f / sbuf[r0], iv1 = 1.f / sbuf[r1];
        float* o0 = out_o + (gq0 + r0) * D;
        float* o1 = out_o + (gq0 + r1) * D;
        #pragma unroll
        for (int nt = 0; nt < 8; ++nt) {
            int c = nt * 8 + cc;
            *(float2*)(o0 + c) = make_float2((oacc[nt][0] + ob[r0 * 64 + c]) * iv0,
                                             (oacc[nt][1] + ob[r0 * 64 + c + 1]) * iv0);
            *(float2*)(o1 + c) = make_float2((oacc[nt][2] + ob[r1 * 64 + c]) * iv1,
                                             (oacc[nt][3] + ob[r1 * 64 + c + 1]) * iv1);
        }
    }
}

// ============ rescale: p = e * inv[row], in place ============
__global__ void __launch_bounds__(256)
rescale_kernel(float* __restrict__ p)
{
    const int row = blockIdx.x * 2 + (threadIdx.x >> 7);
    const float inv = 1.f / g_sums[row];
    float4* pr = (float4*)(p + (size_t)row * S);
    const int c = threadIdx.x & 127;
    #pragma unroll
    for (int i = 0; i < 4; ++i) {
        float4 v = pr[c + i * 128];
        v.x *= inv; v.y *= inv; v.z *= inv; v.w *= inv;
        pr[c + i * 128] = v;
    }
}

extern "C" void kernel_launch(void* const* d_in, const int* in_sizes, int n_in,
                              void* d_out, int out_size)
{
    const float* Q     = (const float*)d_in[0];
    const float* K     = (const float*)d_in[1];
    const float* V     = (const float*)d_in[2];
    const int*   mask  = (const int*)d_in[3];
    const float* decay = (const float*)d_in[4];

    float* out_o = (float*)d_out;
    float* out_p = (float*)d_out + (size_t)BH * S * D;

    cudaFuncSetAttribute(fused_kernel, cudaFuncAttributeMaxDynamicSharedMemorySize, (int)SMEM_F);

    fused_kernel<<<BH * (S / 64), 256, SMEM_F>>>(Q, K, V, mask, decay, out_p, out_o);
    rescale_kernel<<<BH * S / 2, 256>>>(out_p);
}